// round 10
// baseline (speedup 1.0000x reference)
#include <cuda_runtime.h>
#include <cstdint>

// FM second-order term via split-TF32 mma.sync (m16n8k8).
//   sum_emb = features @ W  (M=16384, K=200->208, N=64)
//   x = hi + lo (tf32 split); x@W ~ hi@Whi + hi@Wlo + lo@Whi, fp32 accum.
//   out[b] = sum_e sum_emb[b,e]^2 - sum_f features[b,f]^2 * w2sum[f]
// R10: A staged RAW fp32 via cp.async (no conversion pass!), split to hi/lo
// in registers inside the MMA loop (mask+sub). B pre-converted by prep into
// fragment-linear tf32 hi/lo blocks -> one LDS.128 per n8-tile per kstep.
// 1 CTA/SM, 512 thr, 16 warps = mg4 x ng4, warp tile m32 x n16, full K.

typedef unsigned long long ull;

constexpr int F_DIM = 200;
constexpr int E_DIM = 64;
constexpr int MTILE = 128;
constexpr int THREADS = 512;
constexpr int NS = 26;               // k8-steps (208 >= 200)

constexpr int SA_F = 212;            // A smem row stride (floats; 848B)
constexpr int SM_A    = 0;           // 128*848      = 108544
constexpr int SM_B    = 108544;      // 8*26*512     = 106496
constexpr int SM_W2S  = 215040;      // 200*4
constexpr int SM_SQS  = 215840;      // 128*4
constexpr int SM_PART = 216352;      // 4*128*4
constexpr int SMEM_TOTAL = 218400;

// prep outputs: B fragment-linear: block (t,s) at (t*26+s)*512, lane l holds
// 16B {b0h,b1h,b0l,b1l} with b0=W[8s+l%4][8t+l/4], b1=W[8s+l%4+4][8t+l/4].
__device__ __align__(16) unsigned char gBfrag[106496];
__device__ __align__(16) float gW2s[200];

__device__ __forceinline__ uint32_t smem_u32(const void* p) {
    return (uint32_t)__cvta_generic_to_shared(p);
}
__device__ __forceinline__ void cp_async16(uint32_t s, const void* g) {
    asm volatile("cp.async.cg.shared.global [%0], [%1], 16;" :: "r"(s), "l"(g));
}
__device__ __forceinline__ uint32_t cvt_tf32(float x) {
    uint32_t r; asm("cvt.rna.tf32.f32 %0, %1;" : "=r"(r) : "f"(x)); return r;
}
__device__ __forceinline__ float lds32f(uint32_t a) {
    float v; asm volatile("ld.shared.f32 %0, [%1];" : "=f"(v) : "r"(a)); return v;
}
__device__ __forceinline__ uint4 lds128(uint32_t a) {
    uint4 v;
    asm volatile("ld.shared.v4.b32 {%0,%1,%2,%3}, [%4];"
                 : "=r"(v.x), "=r"(v.y), "=r"(v.z), "=r"(v.w) : "r"(a));
    return v;
}
__device__ __forceinline__ void mma_tf32(float* c, uint32_t a0, uint32_t a1,
                                         uint32_t a2, uint32_t a3,
                                         uint32_t b0, uint32_t b1) {
    asm volatile(
        "mma.sync.aligned.m16n8k8.row.col.f32.tf32.tf32.f32 "
        "{%0,%1,%2,%3}, {%4,%5,%6,%7}, {%8,%9}, {%0,%1,%2,%3};"
        : "+f"(c[0]), "+f"(c[1]), "+f"(c[2]), "+f"(c[3])
        : "r"(a0), "r"(a1), "r"(a2), "r"(a3), "r"(b0), "r"(b1));
}

// ---------------- prep: W -> fragment-linear tf32 hi/lo + w2sum ----------
__global__ void __launch_bounds__(256)
prep_kernel(const float* __restrict__ W)
{
    const int tid = threadIdx.x;
    if (blockIdx.x < 26) {
        const int bi = blockIdx.x * 8 + (tid >> 5);   // 0..207 = (t,s)
        const int l  = tid & 31;
        const int t  = bi / 26, s = bi - 26 * t;
        const int n  = 8 * t + (l >> 2);
        const int k0 = 8 * s + (l & 3);
        const float b0 = (k0 < F_DIM) ? W[(size_t)k0 * E_DIM + n] : 0.f;
        const float b1 = (k0 + 4 < F_DIM) ? W[(size_t)(k0 + 4) * E_DIM + n] : 0.f;
        const uint32_t b0h = cvt_tf32(b0), b1h = cvt_tf32(b1);
        const uint32_t b0l = cvt_tf32(b0 - __uint_as_float(b0h));
        const uint32_t b1l = cvt_tf32(b1 - __uint_as_float(b1h));
        *(uint4*)(gBfrag + (size_t)bi * 512 + l * 16) =
            make_uint4(b0h, b1h, b0l, b1l);
    } else if (tid < F_DIM) {
        const float4* wr = (const float4*)(W + (size_t)tid * E_DIM);
        float s = 0.f;
        #pragma unroll
        for (int i = 0; i < E_DIM / 4; ++i) {
            float4 v = wr[i];
            s = fmaf(v.x, v.x, s); s = fmaf(v.y, v.y, s);
            s = fmaf(v.z, v.z, s); s = fmaf(v.w, v.w, s);
        }
        gW2s[tid] = s;
    }
}

__global__ void __launch_bounds__(THREADS, 1)
fm_kernel(const float* __restrict__ features, float* __restrict__ out)
{
    extern __shared__ __align__(16) char smem[];
    const uint32_t sb = smem_u32(smem);
    const int tid = threadIdx.x;
    const int w = tid >> 5, lane = tid & 31;
    const int mg = w >> 2, ng = w & 3;
    const int gr = lane >> 2, gk = lane & 3;

    float* w2s  = (float*)(smem + SM_W2S);
    float* sqs  = (float*)(smem + SM_SQS);
    float* part = (float*)(smem + SM_PART);

    const size_t rowbase = (size_t)blockIdx.x * MTILE;
    const float* fblk = features + rowbase * F_DIM;

    // ---- cp.async A raw fp32: 128 rows x 50 chunks of 16B
    #pragma unroll
    for (int i = 0; i < 13; ++i) {
        const int p = tid + i * THREADS;
        if (p < 6400) {
            const int row = p / 50, ch = p - row * 50;
            cp_async16(sb + SM_A + row * 848 + ch * 16,
                       fblk + row * F_DIM + ch * 4);
        }
    }
    // ---- cp.async B fragment planes (6656 chunks) + w2s (50 chunks)
    #pragma unroll
    for (int i = 0; i < 13; ++i) {
        const int q = tid + i * THREADS;
        cp_async16(sb + SM_B + q * 16, gBfrag + q * 16);
    }
    if (tid < 50) cp_async16(sb + SM_W2S + tid * 16, (const char*)gW2s + tid * 16);
    asm volatile("cp.async.commit_group;");

    // ---- zero A K-pad cols [200,208) (disjoint bytes from cp.async)
    {
        const int row = tid >> 2, c0 = 200 + (tid & 3) * 2;
        *(float2*)(smem + SM_A + (row * SA_F + c0) * 4) = make_float2(0.f, 0.f);
    }

    asm volatile("cp.async.wait_group 0;" ::: "memory");
    __syncthreads();

    // ---- MMA mainloop: warp tile m32 x n16, full K (26 k8-steps)
    const uint32_t aB = sb + SM_A + (uint32_t)(((32 * mg + gr) * SA_F + gk) * 4);
    const uint32_t bB = sb + SM_B + (uint32_t)((2 * ng * 26) * 512 + lane * 16);

    float c[2][2][4];
    #pragma unroll
    for (int mi = 0; mi < 2; ++mi)
        #pragma unroll
        for (int j = 0; j < 2; ++j)
            #pragma unroll
            for (int q = 0; q < 4; ++q) c[mi][j][q] = 0.f;

    #pragma unroll
    for (int s = 0; s < NS; ++s) {
        // A: 8 fp32, rows 32mg + gr + 8u, cols 8s + gk + 4v  (conflict-free)
        float a[8];
        #pragma unroll
        for (int u = 0; u < 4; ++u)
            #pragma unroll
            for (int v = 0; v < 2; ++v)
                a[u * 2 + v] = lds32f(aB + (uint32_t)(s * 32 + v * 16 + u * 8 * SA_F * 4));
        // split: hi = mask13(x), lo = x - hi (HW ignores lo's low bits)
        uint32_t ah[8], al[8];
        #pragma unroll
        for (int j = 0; j < 8; ++j) {
            ah[j] = __float_as_uint(a[j]) & 0xFFFFE000u;
            al[j] = __float_as_uint(a[j] - __uint_as_float(ah[j]));
        }
        // B frags: one LDS.128 per n8-tile = {b0h,b1h,b0l,b1l}
        const uint4 B0 = lds128(bB + s * 512);
        const uint4 B1 = lds128(bB + 13312 + s * 512);

        // hh (4 independent accums), then hl, then lh
        mma_tf32(c[0][0], ah[0], ah[2], ah[1], ah[3], B0.x, B0.y);
        mma_tf32(c[0][1], ah[0], ah[2], ah[1], ah[3], B1.x, B1.y);
        mma_tf32(c[1][0], ah[4], ah[6], ah[5], ah[7], B0.x, B0.y);
        mma_tf32(c[1][1], ah[4], ah[6], ah[5], ah[7], B1.x, B1.y);

        mma_tf32(c[0][0], ah[0], ah[2], ah[1], ah[3], B0.z, B0.w);
        mma_tf32(c[0][1], ah[0], ah[2], ah[1], ah[3], B1.z, B1.w);
        mma_tf32(c[1][0], ah[4], ah[6], ah[5], ah[7], B0.z, B0.w);
        mma_tf32(c[1][1], ah[4], ah[6], ah[5], ah[7], B1.z, B1.w);

        mma_tf32(c[0][0], al[0], al[2], al[1], al[3], B0.x, B0.y);
        mma_tf32(c[0][1], al[0], al[2], al[1], al[3], B1.x, B1.y);
        mma_tf32(c[1][0], al[4], al[6], al[5], al[7], B0.x, B0.y);
        mma_tf32(c[1][1], al[4], al[6], al[5], al[7], B1.x, B1.y);
    }

    // ---- epilogue: per-row sum of squares over this warp's 16 cols
    {
        float su[4];
        #pragma unroll
        for (int u = 0; u < 4; ++u) {
            const int mi = u >> 1, cr = (u & 1) * 2;
            su[u] = c[mi][0][cr] * c[mi][0][cr] + c[mi][0][cr + 1] * c[mi][0][cr + 1]
                  + c[mi][1][cr] * c[mi][1][cr] + c[mi][1][cr + 1] * c[mi][1][cr + 1];
        }
        #pragma unroll
        for (int u = 0; u < 4; ++u) {
            su[u] += __shfl_xor_sync(0xffffffffu, su[u], 1);
            su[u] += __shfl_xor_sync(0xffffffffu, su[u], 2);
        }
        if (gk == 0) {
            #pragma unroll
            for (int u = 0; u < 4; ++u)
                part[ng * 128 + 32 * mg + 8 * u + gr] = su[u];
        }
    }

    // ---- sq term from smem A (raw fp32): row = tid/4, q covers f = q+4j
    {
        const int row = tid >> 2, q = tid & 3;
        const uint32_t aRow = sb + SM_A + (uint32_t)(row * 848);
        float s0 = 0.f, s1 = 0.f;
        #pragma unroll
        for (int j = 0; j < 50; j += 2) {
            const int f0 = q + 4 * j, f1 = q + 4 * (j + 1);
            const float x0 = lds32f(aRow + f0 * 4);
            const float x1 = lds32f(aRow + f1 * 4);
            s0 = fmaf(x0 * x0, w2s[f0], s0);
            s1 = fmaf(x1 * x1, w2s[f1], s1);
        }
        float sq = s0 + s1;
        sq += __shfl_xor_sync(0xffffffffu, sq, 1);
        sq += __shfl_xor_sync(0xffffffffu, sq, 2);
        if (q == 0) sqs[row] = sq;
    }
    __syncthreads();

    if (tid < MTILE)
        out[rowbase + tid] = part[tid] + part[128 + tid] + part[256 + tid] +
                             part[384 + tid] - sqs[tid];
}

extern "C" void kernel_launch(void* const* d_in, const int* in_sizes, int n_in,
                              void* d_out, int out_size)
{
    const float* features = (const float*)d_in[0];
    const float* W        = (const float*)d_in[1];
    if (n_in >= 2 && in_sizes[0] < in_sizes[1]) {
        features = (const float*)d_in[1];
        W        = (const float*)d_in[0];
    }
    float* out = (float*)d_out;

    cudaFuncSetAttribute(fm_kernel,
                         cudaFuncAttributeMaxDynamicSharedMemorySize, SMEM_TOTAL);

    prep_kernel<<<27, 256>>>(W);

    const int B = out_size;              // 16384
    const int blocks = B / MTILE;        // 128 -> 1 CTA/SM, single wave
    fm_kernel<<<blocks, THREADS, SMEM_TOTAL>>>(features, out);
}